// round 7
// baseline (speedup 1.0000x reference)
#include <cuda_runtime.h>
#include <cstdint>

#define DIM 64
#define KCODES 1024
#define NROWS (32*64*64)
#define QELEMS (NROWS*DIM)
#define THRESH 2e-4f

// smem words: se[1024] | 2 bufs x (2 splits x 128 codes x 68)
#define SE_W   1024
#define SPL_W  8704
#define BUF_W  17408
#define SMEM_W (SE_W + 2*BUF_W)
#define ASTRIDE 260          // A-stage [c][r] word stride (staged in buf0 area)

__device__ float g_se[KCODES];
__device__ float g_bsplit[2][KCODES][68];  // [split][code][tig*16 + g*2 + half] = e[8g+tig+4*half]
__device__ float4 g_res[NROWS];
__device__ float g_losspart[512];

__device__ __forceinline__ uint32_t s2u(const void* p){
    uint32_t a; asm("{ .reg .u64 t; cvta.to.shared.u64 t, %1; cvt.u32.u64 %0, t; }":"=r"(a):"l"(p)); return a;
}
__device__ __forceinline__ void mma_t(float* d, const uint32_t* a, uint32_t b0, uint32_t b1) {
    asm("mma.sync.aligned.m16n8k8.row.col.f32.tf32.tf32.f32 "
        "{%0,%1,%2,%3},{%4,%5,%6,%7},{%8,%9},{%0,%1,%2,%3};"
        : "+f"(d[0]), "+f"(d[1]), "+f"(d[2]), "+f"(d[3])
        : "r"(a[0]), "r"(a[1]), "r"(a[2]), "r"(a[3]), "r"(b0), "r"(b1));
}
#define CPA16(dst, src) asm volatile("cp.async.cg.shared.global [%0], [%1], 16;"::"r"(dst),"l"(src):"memory")
#define CPCOMMIT()      asm volatile("cp.async.commit_group;":::"memory")
#define CPWAIT(n)       asm volatile("cp.async.wait_group %0;"::"n"(n):"memory")

// ---------------- prep: se + pre-split pre-fragged codebook ----------------
__global__ void vq_prep(const float* __restrict__ cb) {
    int k = blockIdx.x * blockDim.x + threadIdx.x;
    if (k >= KCODES) return;
    float s = 0.f;
#pragma unroll
    for (int c = 0; c < DIM; ++c) {
        float v = cb[k*DIM + c];
        s = fmaf(v, v, s);
        float hi = __uint_as_float(__float_as_uint(v) & 0xFFFFE000u);
        int g = c >> 3, k8 = c & 7, tg = k8 & 3, half = k8 >> 2;
        int pos = tg*16 + g*2 + half;
        g_bsplit[0][k][pos] = hi;
        g_bsplit[1][k][pos] = v - hi;
    }
    g_se[k] = s;
}

// ---------------- main: split-tf32 mma.sync scan ---------------------------
__global__ __launch_bounds__(512, 1) void vq_mma(const float* __restrict__ x) {
    extern __shared__ float sm[];
    const uint32_t sb = s2u(sm);
    const int tid = threadIdx.x, w = tid>>5, lane = tid&31;
    const int gid = lane>>2, tig = lane&3;
    const int n0 = blockIdx.x * 256;
    const int b = n0 >> 12, hw0 = n0 & 4095;

    for (int i = tid; i < KCODES; i += 512) sm[i] = g_se[i];

    // Stage A tile [c][r] into buf0 area (coalesced float4 reads).
    const float* xb = x + (size_t)b*262144 + hw0;
    for (int i = tid; i < 4096; i += 512) {
        int c = i >> 6, r4 = (i & 63) << 2;
        *reinterpret_cast<float4*>(sm + SE_W + c*ASTRIDE + r4) =
            *reinterpret_cast<const float4*>(xb + c*4096 + r4);
    }
    __syncthreads();

    // A fragments (hi only): rows r0 = w*16+gid, r0+8
    const int r0 = w*16 + gid;
    uint32_t ah[8][4];
#pragma unroll
    for (int g = 0; g < 8; ++g) {
#pragma unroll
        for (int j = 0; j < 4; ++j) {
            int k = 8*g + tig + (j >> 1)*4;
            int r = r0 + (j & 1)*8;
            float v = sm[SE_W + k*ASTRIDE + r];
            ah[g][j] = __float_as_uint(v) & 0xFFFFE000u;
        }
    }
    __syncthreads();

    // B pipeline: double buffer, 8 chunks of 128 codes.
#define BLOAD(ch) do { int _nb = (ch) & 1, _base = (ch)*128; \
    for (int i = tid; i < 4096; i += 512) { \
        int sp = i >> 11, rem = i & 2047, n = rem >> 4, j4 = (rem & 15) << 2; \
        CPA16(sb + 4*(SE_W + _nb*BUF_W + sp*SPL_W + n*68 + j4), \
              (const void*)&g_bsplit[sp][_base + n][j4]); } \
    CPCOMMIT(); } while (0)

    BLOAD(0); BLOAD(1);

    float d1a = 3e38f, d2a = 3e38f, d1b = 3e38f, d2b = 3e38f;
    int ka = 0, kb = 0;

    for (int c = 0; c < 8; ++c) {
        int buf = c & 1;
        if (c < 7) { CPWAIT(1); } else { CPWAIT(0); }
        __syncthreads();

        const float* base = sm + SE_W + buf*BUF_W;
#pragma unroll 2
        for (int t = 0; t < 16; ++t) {
            int nrow = t*8 + gid;
            const float4* bh = reinterpret_cast<const float4*>(base + nrow*68 + tig*16);
            const float4* bl = reinterpret_cast<const float4*>(base + SPL_W + nrow*68 + tig*16);
            float4 H0 = bh[0], H1 = bh[1], H2 = bh[2], H3 = bh[3];
            float4 L0 = bl[0], L1 = bl[1], L2 = bl[2], L3 = bl[3];
            float hh[4] = {0,0,0,0}, hl[4] = {0,0,0,0};
            mma_t(hh, ah[0], __float_as_uint(H0.x), __float_as_uint(H0.y));
            mma_t(hl, ah[0], __float_as_uint(L0.x), __float_as_uint(L0.y));
            mma_t(hh, ah[1], __float_as_uint(H0.z), __float_as_uint(H0.w));
            mma_t(hl, ah[1], __float_as_uint(L0.z), __float_as_uint(L0.w));
            mma_t(hh, ah[2], __float_as_uint(H1.x), __float_as_uint(H1.y));
            mma_t(hl, ah[2], __float_as_uint(L1.x), __float_as_uint(L1.y));
            mma_t(hh, ah[3], __float_as_uint(H1.z), __float_as_uint(H1.w));
            mma_t(hl, ah[3], __float_as_uint(L1.z), __float_as_uint(L1.w));
            mma_t(hh, ah[4], __float_as_uint(H2.x), __float_as_uint(H2.y));
            mma_t(hl, ah[4], __float_as_uint(L2.x), __float_as_uint(L2.y));
            mma_t(hh, ah[5], __float_as_uint(H2.z), __float_as_uint(H2.w));
            mma_t(hl, ah[5], __float_as_uint(L2.z), __float_as_uint(L2.w));
            mma_t(hh, ah[6], __float_as_uint(H3.x), __float_as_uint(H3.y));
            mma_t(hl, ah[6], __float_as_uint(L3.x), __float_as_uint(L3.y));
            mma_t(hh, ah[7], __float_as_uint(H3.z), __float_as_uint(H3.w));
            mma_t(hl, ah[7], __float_as_uint(L3.z), __float_as_uint(L3.w));

            int kg = c*128 + t*8 + tig*2;
            float2 sep = *reinterpret_cast<const float2*>(sm + kg);
            float s0 = fmaf(hh[0] + hl[0], -2.f, sep.x);
            float s1 = fmaf(hh[1] + hl[1], -2.f, sep.y);
            float s2 = fmaf(hh[2] + hl[2], -2.f, sep.x);
            float s3 = fmaf(hh[3] + hl[3], -2.f, sep.y);
            if (s0 < d1a) { d2a = d1a; d1a = s0; ka = kg; } else if (s0 < d2a) d2a = s0;
            if (s1 < d1a) { d2a = d1a; d1a = s1; ka = kg+1; } else if (s1 < d2a) d2a = s1;
            if (s2 < d1b) { d2b = d1b; d1b = s2; kb = kg; } else if (s2 < d2b) d2b = s2;
            if (s3 < d1b) { d2b = d1b; d1b = s3; kb = kg+1; } else if (s3 < d2b) d2b = s3;
        }
        __syncthreads();
        if (c < 6) BLOAD(c+2);
    }

    const unsigned FULL = 0xffffffffu;
#pragma unroll
    for (int o = 1; o <= 2; o <<= 1) {
        float od1 = __shfl_xor_sync(FULL, d1a, o), od2 = __shfl_xor_sync(FULL, d2a, o);
        int   ok  = __shfl_xor_sync(FULL, ka, o);
        if (od1 < d1a || (od1 == d1a && ok < ka)) { d2a = fminf(d1a, od2); d1a = od1; ka = ok; }
        else d2a = fminf(d2a, od1);
        od1 = __shfl_xor_sync(FULL, d1b, o); od2 = __shfl_xor_sync(FULL, d2b, o);
        ok  = __shfl_xor_sync(FULL, kb, o);
        if (od1 < d1b || (od1 == d1b && ok < kb)) { d2b = fminf(d1b, od2); d1b = od1; kb = ok; }
        else d2b = fminf(d2b, od1);
    }
    if (tig == 0) {
        g_res[n0 + r0]     = make_float4(d1a, d2a, __int_as_float(ka), 0.f);
        g_res[n0 + r0 + 8] = make_float4(d1b, d2b, __int_as_float(kb), 0.f);
    }
}

// ---------------- finalize: exact rescue + outputs -------------------------
__global__ __launch_bounds__(256) void vq_fin(const float* __restrict__ x,
                                              const float* __restrict__ cb,
                                              float* __restrict__ out) {
    __shared__ float xs[8][64];
    __shared__ float red[256];
    const int tid = threadIdx.x, lane = tid&31, wrp = tid>>5;
    const int n = blockIdx.x*256 + tid;
    const unsigned FULL = 0xffffffffu;

    float4 rs = g_res[n];
    int bi = __float_as_int(rs.z);
    int flag = (rs.y - rs.x) < THRESH;
    unsigned m = __ballot_sync(FULL, flag);
    while (m) {
        int src = __ffs(m)-1; m &= m-1;
        int rn = __shfl_sync(FULL, n, src);
        int bb = rn>>12, hw = rn&4095;
        const float* xr = x + (size_t)bb*262144 + hw;
        for (int c = lane; c < 64; c += 32) xs[wrp][c] = xr[c*4096];
        __syncwarp();
        float sx = 0.f;
#pragma unroll
        for (int c = 0; c < 64; ++c) sx = fmaf(xs[wrp][c], xs[wrp][c], sx);
        float bd = 3e38f; int bk = 0;
        for (int k0 = 0; k0 < 32; ++k0) {
            int k = lane*32 + k0;
            const float* e = cb + k*64;
            float P = 0.f;
#pragma unroll
            for (int c = 0; c < 64; ++c) P = fmaf(xs[wrp][c], e[c], P);
            float d = __fadd_rn(__fadd_rn(sx, g_se[k]), __fmul_rn(-2.0f, P));
            if (d < bd) { bd = d; bk = k; }
        }
#pragma unroll
        for (int o = 16; o > 0; o >>= 1) {
            float dv = __shfl_down_sync(FULL, bd, o);
            int   kv = __shfl_down_sync(FULL, bk, o);
            if (dv < bd || (dv == bd && kv < bk)) { bd = dv; bk = kv; }
        }
        int win = __shfl_sync(FULL, bk, 0);
        if (lane == src) bi = win;
        __syncwarp();
    }

    const int bb = n>>12, hw = n&4095;
    const float* xr = x + (size_t)bb*262144 + hw;
    const float* e  = cb + bi*64;
    float* q = out + 1 + (size_t)bb*262144 + hw;
    float lsum = 0.f;
#pragma unroll
    for (int c = 0; c < 64; ++c) {
        float ec = __ldg(e + c);
        float d  = ec - xr[c*4096];
        lsum = fmaf(d, d, lsum);
        q[c*4096] = ec;
    }
    out[1 + QELEMS + n] = (float)bi;

    red[tid] = lsum;
    __syncthreads();
#pragma unroll
    for (int s = 128; s > 0; s >>= 1) {
        if (tid < s) red[tid] += red[tid + s];
        __syncthreads();
    }
    if (tid == 0) g_losspart[blockIdx.x] = red[0];
}

__global__ void vq_loss(float* __restrict__ out) {
    __shared__ float red[512];
    int tid = threadIdx.x;
    red[tid] = g_losspart[tid];
    __syncthreads();
    for (int s = 256; s > 0; s >>= 1) {
        if (tid < s) red[tid] += red[tid + s];
        __syncthreads();
    }
    if (tid == 0) out[0] = red[0] * (1.25f / (float)QELEMS);
}

extern "C" void kernel_launch(void* const* d_in, const int* in_sizes, int n_in,
                              void* d_out, int out_size) {
    const float* x  = (const float*)d_in[0];
    const float* cb = (const float*)d_in[1];
    float* out = (float*)d_out;
    cudaFuncSetAttribute(vq_mma, cudaFuncAttributeMaxDynamicSharedMemorySize, SMEM_W*4);
    vq_prep<<<4, 256>>>(cb);
    vq_mma<<<NROWS/256, 512, SMEM_W*4>>>(x);
    vq_fin<<<NROWS/256, 256>>>(x, cb, out);
    vq_loss<<<1, 512>>>(out);
}

// round 8
// speedup vs baseline: 7.3695x; 7.3695x over previous
#include <cuda_runtime.h>
#include <cstdint>

// VQ-VAE quantizer — bit-faithful fp32 argmin (R4 math), FFMA2 mainloop,
// 4 rows/thread, cp.async double-buffered pair-interleaved codebook.
// out f32: [ loss(1) | quantized NCHW (8388608) | idx (131072) ]

#define TPB 128
#define RPB 512
#define RSTRIDE 68
#define DIM 64
#define KCODES 1024
#define NROWS (32*64*64)
#define NB (NROWS/RPB)          // 256 CTAs
#define QELEMS (NROWS*DIM)

// smem words
#define XS_W 0                  // 512*68 = 34816
#define ES_W 34816              // 2 bufs x 4096
#define SES_W 43008             // 1024
#define RED_W 44032             // 128
#define SMEM_B ((RED_W + 128) * 4)

__device__ float g_se[KCODES];
__device__ float g_pair[KCODES/2][128];  // [k>>1][c*2 + (k&1)] = cb[k][c]
__device__ float g_losspart[NB];

typedef unsigned long long u64;
__device__ __forceinline__ uint32_t s2u(const void* p){
    uint32_t a; asm("{ .reg .u64 t; cvta.to.shared.u64 t, %1; cvt.u32.u64 %0, t; }":"=r"(a):"l"(p)); return a;
}
__device__ __forceinline__ void fma2(u64& acc, u64 a, u64 b) {
    asm("fma.rn.f32x2 %0, %1, %2, %3;" : "=l"(acc) : "l"(a), "l"(b), "l"(acc));
}
__device__ __forceinline__ u64 bcast2(float x) {
    u64 d; unsigned r = __float_as_uint(x);
    asm("mov.b64 %0, {%1,%1};" : "=l"(d) : "r"(r));
    return d;
}
__device__ __forceinline__ void unpack2(u64 v, float& lo, float& hi) {
    unsigned a, b;
    asm("mov.b64 {%0,%1}, %2;" : "=r"(a), "=r"(b) : "l"(v));
    lo = __uint_as_float(a); hi = __uint_as_float(b);
}
#define CPA16(dst, src) asm volatile("cp.async.cg.shared.global [%0], [%1], 16;"::"r"(dst),"l"(src):"memory")
#define CPCOMMIT()      asm volatile("cp.async.commit_group;":::"memory")
#define CPWAIT(n)       asm volatile("cp.async.wait_group %0;"::"n"(n):"memory")

// ---------------- prep: se + pair-interleaved codebook ---------------------
__global__ void vq_prep(const float* __restrict__ cb) {
    int k = blockIdx.x * blockDim.x + threadIdx.x;
    if (k >= KCODES) return;
    float s = 0.f;
#pragma unroll
    for (int c = 0; c < DIM; ++c) {
        float v = cb[k*DIM + c];
        s = fmaf(v, v, s);
        g_pair[k >> 1][c*2 + (k & 1)] = v;
    }
    g_se[k] = s;
}

// ---------------- main ------------------------------------------------------
__global__ __launch_bounds__(TPB, 1) void vq_main(const float* __restrict__ x,
                                                  const float* __restrict__ cb,
                                                  float* __restrict__ out) {
    extern __shared__ float sm[];
    const uint32_t sb = s2u(sm);
    const int tid = threadIdx.x;
    const int n0 = blockIdx.x * RPB;
    const int b = n0 >> 12, off = n0 & 4095;
    const float* xb = x + (size_t)b*262144 + off;

#define BLOAD(ch) do { int _bf = (ch) & 1; \
    for (int i = tid; i < 1024; i += TPB) \
        CPA16(sb + 4*(ES_W + _bf*4096 + i*4), (const char*)g_pair + (ch)*16384 + i*16); \
    CPCOMMIT(); } while (0)

    BLOAD(0);

    // x tile -> smem [r][c] stride 68 (coalesced float4 over rows)
    for (int i = tid; i < DIM * (RPB/4); i += TPB) {
        int c = i >> 7, r4 = (i & 127) << 2;
        float4 v = *reinterpret_cast<const float4*>(xb + c*4096 + r4);
        sm[XS_W + (r4+0)*RSTRIDE + c] = v.x;
        sm[XS_W + (r4+1)*RSTRIDE + c] = v.y;
        sm[XS_W + (r4+2)*RSTRIDE + c] = v.z;
        sm[XS_W + (r4+3)*RSTRIDE + c] = v.w;
    }
    for (int i = tid; i < KCODES; i += TPB) sm[SES_W + i] = g_se[i];
    BLOAD(1);
    __syncthreads();

    // per-row |x|^2
    float sx[4];
#pragma unroll
    for (int j = 0; j < 4; ++j) {
        const float* xr = sm + XS_W + (tid + j*TPB)*RSTRIDE;
        float s = 0.f;
#pragma unroll
        for (int c = 0; c < DIM; ++c) s = fmaf(xr[c], xr[c], s);
        sx[j] = s;
    }

    float best[4] = {3e38f, 3e38f, 3e38f, 3e38f};
    int bidx[4] = {0, 0, 0, 0};

    for (int cc = 0; cc < 16; ++cc) {
        int buf = cc & 1;
        CPWAIT(1);
        __syncthreads();
        const float* eb = sm + ES_W + buf*4096;

        for (int kg = 0; kg < 4; ++kg) {
            u64 acc[4][8];
#pragma unroll
            for (int j = 0; j < 4; ++j)
#pragma unroll
                for (int p = 0; p < 8; ++p) acc[j][p] = 0ull;

#pragma unroll 4
            for (int c4 = 0; c4 < 16; ++c4) {
                u64 a[4][4];
#pragma unroll
                for (int j = 0; j < 4; ++j) {
                    float4 xa = *reinterpret_cast<const float4*>(
                        sm + XS_W + (tid + j*TPB)*RSTRIDE + c4*4);
                    a[j][0] = bcast2(xa.x); a[j][1] = bcast2(xa.y);
                    a[j][2] = bcast2(xa.z); a[j][3] = bcast2(xa.w);
                }
#pragma unroll
                for (int p = 0; p < 8; ++p) {
                    const u64* ep = reinterpret_cast<const u64*>(eb + (kg*8+p)*128 + c4*8);
                    ulonglong2 eA = *reinterpret_cast<const ulonglong2*>(ep);
                    ulonglong2 eB = *reinterpret_cast<const ulonglong2*>(ep + 2);
#pragma unroll
                    for (int j = 0; j < 4; ++j) {
                        fma2(acc[j][p], a[j][0], eA.x); fma2(acc[j][p], a[j][1], eA.y);
                        fma2(acc[j][p], a[j][2], eB.x); fma2(acc[j][p], a[j][3], eB.y);
                    }
                }
            }
#pragma unroll
            for (int p = 0; p < 8; ++p) {
                int ke = cc*64 + kg*16 + 2*p;
                float2 se2 = *reinterpret_cast<const float2*>(sm + SES_W + ke);
#pragma unroll
                for (int j = 0; j < 4; ++j) {
                    float Pe, Po;
                    unpack2(acc[j][p], Pe, Po);
                    float de = __fadd_rn(__fadd_rn(sx[j], se2.x), __fmul_rn(-2.0f, Pe));
                    float dd = __fadd_rn(__fadd_rn(sx[j], se2.y), __fmul_rn(-2.0f, Po));
                    if (de < best[j]) { best[j] = de; bidx[j] = ke; }
                    if (dd < best[j]) { best[j] = dd; bidx[j] = ke + 1; }
                }
            }
        }
        __syncthreads();
        if (cc + 2 < 16) BLOAD(cc + 2);
    }

    // epilogue: gather q (NCHW coalesced per c), idx, loss
    float lsum = 0.f;
    float* qout = out + 1;
    float* iout = out + 1 + QELEMS;
#pragma unroll 1
    for (int j = 0; j < 4; ++j) {
        int row = tid + j*TPB;
        int code = bidx[j];
        const float* e = cb + code*DIM;
        float* q = qout + (size_t)b*262144 + off + row;
#pragma unroll
        for (int c = 0; c < DIM; ++c) {
            float ec = __ldg(e + c);
            float d = ec - sm[XS_W + row*RSTRIDE + c];
            lsum = fmaf(d, d, lsum);
            q[c*4096] = ec;
        }
        iout[n0 + row] = (float)code;
    }

    float* red = sm + RED_W;
    red[tid] = lsum;
    __syncthreads();
#pragma unroll
    for (int s = TPB/2; s > 0; s >>= 1) {
        if (tid < s) red[tid] += red[tid + s];
        __syncthreads();
    }
    if (tid == 0) g_losspart[blockIdx.x] = red[0];
}

__global__ void vq_loss(float* __restrict__ out) {
    __shared__ float red[NB];
    int tid = threadIdx.x;
    red[tid] = g_losspart[tid];
    __syncthreads();
    for (int s = NB/2; s > 0; s >>= 1) {
        if (tid < s) red[tid] += red[tid + s];
        __syncthreads();
    }
    if (tid == 0) out[0] = red[0] * (1.25f / (float)QELEMS);
}

extern "C" void kernel_launch(void* const* d_in, const int* in_sizes, int n_in,
                              void* d_out, int out_size) {
    const float* x  = (const float*)d_in[0];
    const float* cb = (const float*)d_in[1];
    float* out = (float*)d_out;
    cudaFuncSetAttribute(vq_main, cudaFuncAttributeMaxDynamicSharedMemorySize, SMEM_B);
    vq_prep<<<4, 256>>>(cb);
    vq_main<<<NB, TPB, SMEM_B>>>(x, cb, out);
    vq_loss<<<1, NB>>>(out);
}